// round 2
// baseline (speedup 1.0000x reference)
#include <cuda_runtime.h>
#include <cstdint>

// ---------------------------------------------------------------------------
// HausdorffLoss: B=8, N=M=4096, 3-D points.
// d[b,n,m] = x2[n] + y2[m] - 2*dot(x_n, y_m)
// dist1[n] = min_m d ; dist2[m] = min_n d
// out = sum_b max( max_n dist1, max_m dist2 )
//
// Strategy: one kernel handles both directions (blockIdx.z). Each block owns
// 256 rows and scans all 4096 cols through a shared tile holding
// (-2y0,-2y1,-2y2, y^2) packed pairwise for f32x2 FMAs. Row constant x^2 is
// added after the min. Block max -> atomicMax per batch -> finalize sum.
// ---------------------------------------------------------------------------

#define NPOINT 4096
#define T      128      // threads per block
#define RN     2        // rows per thread
#define BN     (T * RN) // 256 rows per block
#define TM     512      // column tile size (shared): 512 pts * 16B = 8KB

#define FMA2(d, a, b, c) \
    asm("fma.rn.f32x2 %0, %1, %2, %3;" : "=l"(d) : "l"(a), "l"(b), "l"(c))
#define PACK2(o, x) \
    asm("mov.b64 %0, {%1, %1};" : "=l"(o) : "f"(x))
#define UNPACK2(lo, hi, v) \
    asm("mov.b64 {%0, %1}, %2;" : "=f"(lo), "=f"(hi) : "l"(v))

__device__ float g_bmax[64];

__global__ void hd_zero(int nb) {
    if (threadIdx.x < nb) g_bmax[threadIdx.x] = 0.0f;
}

__global__ void __launch_bounds__(T) hd_kernel(const float* __restrict__ p1,
                                               const float* __restrict__ p2) {
    const int tid = threadIdx.x;
    const int b   = blockIdx.y;
    const int dir = blockIdx.z;

    const float* rows = (dir == 0 ? p1 : p2) + (size_t)b * NPOINT * 3;
    const float* cols = (dir == 0 ? p2 : p1) + (size_t)b * NPOINT * 3;

    // Per-thread row points: coords packed (x,x) for f32x2 broadcast.
    unsigned long long px0[RN], px1[RN], px2[RN];
    float xsq[RN];
    float rmE[RN], rmO[RN];   // running min over even / odd column lanes

#pragma unroll
    for (int r = 0; r < RN; r++) {
        const int n = blockIdx.x * BN + r * T + tid;
        const float* pr = rows + (size_t)n * 3;
        const float a0 = pr[0], a1 = pr[1], a2 = pr[2];
        xsq[r] = a0 * a0 + a1 * a1 + a2 * a2;
        PACK2(px0[r], a0);
        PACK2(px1[r], a1);
        PACK2(px2[r], a2);
        rmE[r] = 3.4e38f;
        rmO[r] = 3.4e38f;
    }

    // Shared tile: for column pair j, entry 2j   = {-2y0[e],-2y0[o],-2y1[e],-2y1[o]}
    //                                 entry 2j+1 = {-2y2[e],-2y2[o],  y2[e],  y2[o]}
    __shared__ ulonglong2 sAB[TM];
    __shared__ float wmax[T / 32];

    for (int t0 = 0; t0 < NPOINT; t0 += TM) {
        __syncthreads();
        for (int idx = tid; idx < TM; idx += T) {
            const float* pc = cols + (size_t)(t0 + idx) * 3;
            const float y0 = pc[0], y1 = pc[1], y2 = pc[2];
            const float ysq = y0 * y0 + y1 * y1 + y2 * y2;
            const int j = idx >> 1, l = idx & 1;
            float* A  = reinterpret_cast<float*>(&sAB[2 * j]);
            float* Bv = reinterpret_cast<float*>(&sAB[2 * j + 1]);
            A[l]      = -2.0f * y0;
            A[2 + l]  = -2.0f * y1;
            Bv[l]     = -2.0f * y2;
            Bv[2 + l] = ysq;
        }
        __syncthreads();

#pragma unroll 4
        for (int j = 0; j < TM / 2; j++) {
            const ulonglong2 va = sAB[2 * j];
            const ulonglong2 vb = sAB[2 * j + 1];
#pragma unroll
            for (int r = 0; r < RN; r++) {
                unsigned long long t0r, t1r, acc;
                FMA2(t0r, px2[r], vb.x, vb.y);   // -2*x2*y2 + y^2
                FMA2(t1r, px1[r], va.y, t0r);    // + -2*x1*y1
                FMA2(acc, px0[r], va.x, t1r);    // + -2*x0*y0  => y^2 - 2 x.y
                float lo, hi;
                UNPACK2(lo, hi, acc);
                rmE[r] = fminf(rmE[r], lo);
                rmO[r] = fminf(rmO[r], hi);
            }
        }
    }

    // Thread max of (x^2 + row min)
    float tmax = -3.4e38f;
#pragma unroll
    for (int r = 0; r < RN; r++)
        tmax = fmaxf(tmax, xsq[r] + fminf(rmE[r], rmO[r]));

    // Warp reduce max
#pragma unroll
    for (int off = 16; off > 0; off >>= 1)
        tmax = fmaxf(tmax, __shfl_xor_sync(0xffffffffu, tmax, off));
    if ((tid & 31) == 0) wmax[tid >> 5] = tmax;
    __syncthreads();
    if (tid == 0) {
        float m = wmax[0];
#pragma unroll
        for (int w = 1; w < T / 32; w++) m = fmaxf(m, wmax[w]);
        // True max is strictly positive; clamp keeps int-punned atomicMax exact.
        m = fmaxf(m, 0.0f);
        atomicMax(reinterpret_cast<int*>(&g_bmax[b]), __float_as_int(m));
    }
}

__global__ void hd_final(float* __restrict__ out, int nb) {
    float s = 0.0f;
    for (int i = 0; i < nb; i++) s += g_bmax[i];
    out[0] = s;
}

extern "C" void kernel_launch(void* const* d_in, const int* in_sizes, int n_in,
                              void* d_out, int out_size) {
    const float* p1 = (const float*)d_in[0];
    const float* p2 = (const float*)d_in[1];
    float* out = (float*)d_out;

    const int B = in_sizes[0] / (NPOINT * 3);

    hd_zero<<<1, 64>>>(B);
    dim3 grid(NPOINT / BN, B, 2);
    hd_kernel<<<grid, T>>>(p1, p2);
    hd_final<<<1, 1>>>(out, B);
}

// round 3
// speedup vs baseline: 1.0713x; 1.0713x over previous
#include <cuda_runtime.h>
#include <cstdint>

// ---------------------------------------------------------------------------
// HausdorffLoss: B=8, N=M=4096, 3-D points. Single fused kernel.
// d[b,n,m] = x2[n] + y2[m] - 2*dot(x_n, y_m)
// out = sum_b max( max_n min_m d, max_m min_n d )
//
// grid(8, B, 2): dir 0 = p1 rows vs p2 cols, dir 1 = transposed.
// Block: 256 threads, RN=2 rows/thread -> 512 rows, scans all 4096 cols
// through an 8KB shared tile of (-2y0,-2y1,-2y2,y^2) packed for f32x2 FMAs.
// x^2 (row const) factors out of the min. Block max -> atomicMax[b] ->
// ticket counter -> last block sums 8 slots, writes out, resets globals
// (so every graph replay sees identical initial state).
// ---------------------------------------------------------------------------

#define NPOINT 4096
#define T      256      // threads per block
#define RN     2        // rows per thread
#define BN     (T * RN) // 512 rows per block
#define TM     512      // column tile (shared): 512 pts * 16B = 8KB

#define FMA2(d, a, b, c) \
    asm("fma.rn.f32x2 %0, %1, %2, %3;" : "=l"(d) : "l"(a), "l"(b), "l"(c))
#define PACK2(o, x) \
    asm("mov.b64 %0, {%1, %1};" : "=l"(o) : "f"(x))
#define UNPACK2(lo, hi, v) \
    asm("mov.b64 {%0, %1}, %2;" : "=f"(lo), "=f"(hi) : "l"(v))

__device__ float g_bmax[64];   // zero-init; reset by last block each call
__device__ int   g_done;       // zero-init; reset by last block each call

__global__ void __launch_bounds__(T, 1)
hd_main(const float* __restrict__ p1, const float* __restrict__ p2,
        float* __restrict__ out, int nb, int total_blocks) {
    const int tid = threadIdx.x;
    const int b   = blockIdx.y;
    const int dir = blockIdx.z;

    const float* rows = (dir == 0 ? p1 : p2) + (size_t)b * NPOINT * 3;
    const float* cols = (dir == 0 ? p2 : p1) + (size_t)b * NPOINT * 3;

    // Per-thread row points, coords broadcast-packed for f32x2.
    unsigned long long px0[RN], px1[RN], px2[RN];
    float xsq[RN], rmE[RN], rmO[RN];

#pragma unroll
    for (int r = 0; r < RN; r++) {
        const int n = blockIdx.x * BN + r * T + tid;
        const float* pr = rows + (size_t)n * 3;
        const float a0 = pr[0], a1 = pr[1], a2 = pr[2];
        xsq[r] = a0 * a0 + a1 * a1 + a2 * a2;
        PACK2(px0[r], a0);
        PACK2(px1[r], a1);
        PACK2(px2[r], a2);
        rmE[r] = 3.4e38f;
        rmO[r] = 3.4e38f;
    }

    // Shared tile: col pair j -> entry 2j   = {-2y0[e],-2y0[o],-2y1[e],-2y1[o]}
    //                            entry 2j+1 = {-2y2[e],-2y2[o],  y2[e],  y2[o]}
    __shared__ ulonglong2 sAB[TM];
    __shared__ float wmax[T / 32];

    for (int t0 = 0; t0 < NPOINT; t0 += TM) {
        __syncthreads();
#pragma unroll
        for (int ii = 0; ii < TM / T; ii++) {
            const int idx = ii * T + tid;
            const float* pc = cols + (size_t)(t0 + idx) * 3;
            const float y0 = pc[0], y1 = pc[1], y2 = pc[2];
            const float ysq = y0 * y0 + y1 * y1 + y2 * y2;
            const int j = idx >> 1, l = idx & 1;
            float* A  = reinterpret_cast<float*>(&sAB[2 * j]);
            float* Bv = reinterpret_cast<float*>(&sAB[2 * j + 1]);
            A[l]      = -2.0f * y0;
            A[2 + l]  = -2.0f * y1;
            Bv[l]     = -2.0f * y2;
            Bv[2 + l] = ysq;
        }
        __syncthreads();

#pragma unroll 8
        for (int j = 0; j < TM / 2; j++) {
            const ulonglong2 va = sAB[2 * j];
            const ulonglong2 vb = sAB[2 * j + 1];
#pragma unroll
            for (int r = 0; r < RN; r++) {
                unsigned long long t0r, t1r, acc;
                FMA2(t0r, px2[r], vb.x, vb.y);   // -2*x2*y2 + y^2
                FMA2(t1r, px1[r], va.y, t0r);    // + -2*x1*y1
                FMA2(acc, px0[r], va.x, t1r);    // + -2*x0*y0
                float lo, hi;
                UNPACK2(lo, hi, acc);
                rmE[r] = fminf(rmE[r], lo);
                rmO[r] = fminf(rmO[r], hi);
            }
        }
    }

    // max over this thread's rows of (x^2 + rowmin)
    float tmax = -3.4e38f;
#pragma unroll
    for (int r = 0; r < RN; r++)
        tmax = fmaxf(tmax, xsq[r] + fminf(rmE[r], rmO[r]));

#pragma unroll
    for (int off = 16; off > 0; off >>= 1)
        tmax = fmaxf(tmax, __shfl_xor_sync(0xffffffffu, tmax, off));
    if ((tid & 31) == 0) wmax[tid >> 5] = tmax;
    __syncthreads();

    if (tid == 0) {
        float m = wmax[0];
#pragma unroll
        for (int w = 1; w < T / 32; w++) m = fmaxf(m, wmax[w]);
        m = fmaxf(m, 0.0f);  // keep int-punned atomicMax order-correct
        atomicMax(reinterpret_cast<int*>(&g_bmax[b]), __float_as_int(m));
        __threadfence();
        const int ticket = atomicAdd(&g_done, 1);
        if (ticket == total_blocks - 1) {
            float s = 0.0f;
            for (int i = 0; i < nb; i++)
                s += atomicExch(&g_bmax[i], 0.0f);   // read + reset
            out[0] = s;
            atomicExch(&g_done, 0);                  // reset for next replay
        }
    }
}

extern "C" void kernel_launch(void* const* d_in, const int* in_sizes, int n_in,
                              void* d_out, int out_size) {
    const float* p1 = (const float*)d_in[0];
    const float* p2 = (const float*)d_in[1];
    float* out = (float*)d_out;

    const int B = in_sizes[0] / (NPOINT * 3);
    dim3 grid(NPOINT / BN, B, 2);
    const int total = (NPOINT / BN) * B * 2;

    hd_main<<<grid, T>>>(p1, p2, out, B, total);
}

// round 4
// speedup vs baseline: 1.1153x; 1.0411x over previous
#include <cuda_runtime.h>
#include <cstdint>

// ---------------------------------------------------------------------------
// HausdorffLoss: B=8, N=M=4096, 3-D points. Single fused kernel.
// d[b,n,m] = x2[n] + y2[m] - 2*dot(x_n, y_m)
// out = sum_b max( max_n min_m d, max_m min_n d )
//
// grid (ROWB=4, CS=4, B*2=16) = 256 blocks, 2 co-resident/SM (16 warps/SM).
// Block: 256 threads x RN=4 rows = 1024 rows, scans a 1024-column slice
// through a 16KB shared tile of (-2y0,-2y1,-2y2,y^2) packed for f32x2 FMAs.
// Cross-block per-row min combine: order-inverted-key atomicMax (init 0).
// Per-(b,dir) ticket -> group finalizer max -> per-batch atomicMax ->
// global ticket -> final sum. All state reset for graph-replay invariance.
// ---------------------------------------------------------------------------

#define NPOINT 4096
#define T      256                 // threads per block
#define RN     4                   // rows per thread
#define BN     (T * RN)            // 1024 rows per block
#define ROWB   (NPOINT / BN)       // 4 row-blocks
#define CS     4                   // column splits
#define CPB    (NPOINT / CS)       // 1024 cols per block
#define TM     1024                // column tile = whole slice (16KB)
#define NGRP   16                  // B*2 (b,dir) groups

#define FMA2(d, a, b, c) \
    asm("fma.rn.f32x2 %0, %1, %2, %3;" : "=l"(d) : "l"(a), "l"(b), "l"(c))
#define PACK2(o, x) \
    asm("mov.b64 %0, {%1, %1};" : "=l"(o) : "f"(x))
#define UNPACK2(lo, hi, v) \
    asm("mov.b64 {%0, %1}, %2;" : "=f"(lo), "=f"(hi) : "l"(v))

// Monotone map: smaller float  <=>  LARGER key (so per-row min == atomicMax).
// All real floats map to key > 0, so 0 is the identity/reset state.
__device__ __forceinline__ unsigned map_min(float f) {
    unsigned u = __float_as_uint(f);
    return ((int)u < 0) ? u : (~u & 0x7FFFFFFFu);
}
__device__ __forceinline__ float unmap_min(unsigned s) {
    return ((int)s < 0) ? __uint_as_float(s)
                        : __uint_as_float(~s & 0x7FFFFFFFu);
}

__device__ unsigned g_cmb[NGRP][NPOINT];  // combined row-min keys (reset to 0)
__device__ int      g_grp[NGRP];          // per-group block tickets (reset to 0)
__device__ float    g_bmax[16];           // per-batch max, >=0 (reset to 0)
__device__ int      g_done;               // group-finalizer ticket (reset to 0)

__global__ void __launch_bounds__(T, 2)
hd_main(const float* __restrict__ p1, const float* __restrict__ p2,
        float* __restrict__ out, int nb) {
    const int tid = threadIdx.x;
    const int z   = blockIdx.z;          // b*2 + dir
    const int b   = z >> 1;
    const int dir = z & 1;

    const float* rows = (dir == 0 ? p1 : p2) + (size_t)b * NPOINT * 3;
    const float* cols = (dir == 0 ? p2 : p1) + (size_t)b * NPOINT * 3;

    // Per-thread row points, coords broadcast-packed for f32x2.
    unsigned long long px0[RN], px1[RN], px2[RN];
    float xsq[RN], rmE[RN], rmO[RN];

#pragma unroll
    for (int r = 0; r < RN; r++) {
        const int n = blockIdx.x * BN + r * T + tid;
        const float* pr = rows + (size_t)n * 3;
        const float a0 = pr[0], a1 = pr[1], a2 = pr[2];
        xsq[r] = a0 * a0 + a1 * a1 + a2 * a2;
        PACK2(px0[r], a0);
        PACK2(px1[r], a1);
        PACK2(px2[r], a2);
        rmE[r] = 3.4e38f;
        rmO[r] = 3.4e38f;
    }

    // Shared tile: col pair j -> entry 2j   = {-2y0[e],-2y0[o],-2y1[e],-2y1[o]}
    //                            entry 2j+1 = {-2y2[e],-2y2[o],  y2[e],  y2[o]}
    __shared__ ulonglong2 sAB[TM];
    __shared__ unsigned   sred[T / 32];

    {
        const int c0 = blockIdx.y * CPB;
#pragma unroll
        for (int ii = 0; ii < TM / T; ii++) {
            const int idx = ii * T + tid;
            const float* pc = cols + (size_t)(c0 + idx) * 3;
            const float y0 = pc[0], y1 = pc[1], y2 = pc[2];
            const float ysq = y0 * y0 + y1 * y1 + y2 * y2;
            const int j = idx >> 1, l = idx & 1;
            float* A  = reinterpret_cast<float*>(&sAB[2 * j]);
            float* Bv = reinterpret_cast<float*>(&sAB[2 * j + 1]);
            A[l]      = -2.0f * y0;
            A[2 + l]  = -2.0f * y1;
            Bv[l]     = -2.0f * y2;
            Bv[2 + l] = ysq;
        }
    }
    __syncthreads();

    const ulonglong2* sp = sAB;
#pragma unroll 8
    for (int j = 0; j < TM / 2; j++, sp += 2) {
        const ulonglong2 va = sp[0];
        const ulonglong2 vb = sp[1];
#pragma unroll
        for (int r = 0; r < RN; r++) {
            unsigned long long t0r, t1r, acc;
            FMA2(t0r, px2[r], vb.x, vb.y);   // -2*x2*y2 + y^2
            FMA2(t1r, px1[r], va.y, t0r);    // + -2*x1*y1
            FMA2(acc, px0[r], va.x, t1r);    // + -2*x0*y0
            float lo, hi;
            UNPACK2(lo, hi, acc);
            rmE[r] = fminf(rmE[r], lo);
            rmO[r] = fminf(rmO[r], hi);
        }
    }

    // Combine this slice's row mins into the global per-row key array.
#pragma unroll
    for (int r = 0; r < RN; r++) {
        const int n = blockIdx.x * BN + r * T + tid;
        const float d = xsq[r] + fminf(rmE[r], rmO[r]);
        atomicMax(&g_cmb[z][n], map_min(d));
    }
    __threadfence();
    __syncthreads();

    // Group ticket: last of the ROWB*CS blocks in this (b,dir) finalizes.
    __shared__ int s_last;
    if (tid == 0)
        s_last = (atomicAdd(&g_grp[z], 1) == ROWB * CS - 1);
    __syncthreads();
    if (!s_last) return;
    __threadfence();

    // Group finalize: max over rows of row-min == unmap(min over keys).
    unsigned kmin = 0xFFFFFFFFu;
    for (int i = tid; i < NPOINT; i += T) {
        kmin = min(kmin, g_cmb[z][i]);
        g_cmb[z][i] = 0u;                       // reset for next replay
    }
#pragma unroll
    for (int off = 16; off > 0; off >>= 1)
        kmin = min(kmin, __shfl_xor_sync(0xffffffffu, kmin, off));
    if ((tid & 31) == 0) sred[tid >> 5] = kmin;
    __syncthreads();

    if (tid == 0) {
        unsigned km = sred[0];
#pragma unroll
        for (int w = 1; w < T / 32; w++) km = min(km, sred[w]);
        float m = fmaxf(unmap_min(km), 0.0f);   // true max > 0; clamp keeps
        atomicMax(reinterpret_cast<int*>(&g_bmax[b]), __float_as_int(m));
        g_grp[z] = 0;                           // reset group ticket
        __threadfence();
        if (atomicAdd(&g_done, 1) == NGRP - 1) {
            __threadfence();
            float s = 0.0f;
            for (int i = 0; i < nb; i++) {
                s += g_bmax[i];
                g_bmax[i] = 0.0f;               // reset
            }
            out[0] = s;
            __threadfence();
            atomicExch(&g_done, 0);             // reset
        }
    }
}

extern "C" void kernel_launch(void* const* d_in, const int* in_sizes, int n_in,
                              void* d_out, int out_size) {
    const float* p1 = (const float*)d_in[0];
    const float* p2 = (const float*)d_in[1];
    float* out = (float*)d_out;

    const int B = in_sizes[0] / (NPOINT * 3);
    dim3 grid(ROWB, CS, B * 2);
    hd_main<<<grid, T>>>(p1, p2, out, B);
}

// round 5
// speedup vs baseline: 1.3858x; 1.2426x over previous
#include <cuda_runtime.h>
#include <cstdint>

// ---------------------------------------------------------------------------
// HausdorffLoss: B=8, N=M=4096, 3-D points. Single fused kernel.
// d[b,n,m] = x2[n] + y2[m] - 2*dot(x_n, y_m)
// out = sum_b max( max_n min_m d, max_m min_n d )
//
// Round-5 shape: T=128, RN=4 (512 rows/block), CS=16 (256-col slice, 4KB
// tile), grid (8,16,16)=2048 blocks, __launch_bounds__(128,8) -> 64 regs,
// 8 blocks/SM = 32 warps/SM (50% occ) to hide LDS/FFMA2 latency.
// Cross-block per-row min via order-inverted-key atomicMax (identity 0).
// Group ticket (128 blocks) -> group max -> per-batch atomicMax -> global
// ticket -> final sum. All global state reset for graph-replay invariance.
// ---------------------------------------------------------------------------

#define NPOINT 4096
#define T      128                 // threads per block
#define RN     4                   // rows per thread
#define BN     (T * RN)            // 512 rows per block
#define ROWB   (NPOINT / BN)       // 8 row-blocks
#define CS     16                  // column splits
#define CPB    (NPOINT / CS)       // 256 cols per block
#define TM     CPB                 // tile = whole slice (4KB)
#define NGRP   16                  // B*2 (b,dir) groups
#define GBLK   (ROWB * CS)         // blocks per group = 128

#define FMA2(d, a, b, c) \
    asm("fma.rn.f32x2 %0, %1, %2, %3;" : "=l"(d) : "l"(a), "l"(b), "l"(c))
#define PACK2(o, x) \
    asm("mov.b64 %0, {%1, %1};" : "=l"(o) : "f"(x))
#define UNPACK2(lo, hi, v) \
    asm("mov.b64 {%0, %1}, %2;" : "=f"(lo), "=f"(hi) : "l"(v))

// Monotone map: smaller float <=> LARGER unsigned key (row min == atomicMax).
// Every real float maps to key > 0, so 0 is the identity/reset state.
__device__ __forceinline__ unsigned map_min(float f) {
    unsigned u = __float_as_uint(f);
    return ((int)u < 0) ? u : (~u & 0x7FFFFFFFu);
}
__device__ __forceinline__ float unmap_min(unsigned s) {
    return ((int)s < 0) ? __uint_as_float(s)
                        : __uint_as_float(~s & 0x7FFFFFFFu);
}

__device__ unsigned g_cmb[NGRP][NPOINT];  // combined row-min keys (reset 0)
__device__ int      g_grp[NGRP];          // per-group tickets (reset 0)
__device__ float    g_bmax[16];           // per-batch max >= 0 (reset 0)
__device__ int      g_done;               // finalizer ticket (reset 0)

__global__ void __launch_bounds__(T, 8)
hd_main(const float* __restrict__ p1, const float* __restrict__ p2,
        float* __restrict__ out, int nb) {
    const int tid = threadIdx.x;
    const int z   = blockIdx.z;          // b*2 + dir
    const int b   = z >> 1;
    const int dir = z & 1;

    const float* rows = (dir == 0 ? p1 : p2) + (size_t)b * NPOINT * 3;
    const float* cols = (dir == 0 ? p2 : p1) + (size_t)b * NPOINT * 3;

    // Per-thread row points, coords broadcast-packed for f32x2.
    unsigned long long px0[RN], px1[RN], px2[RN];
    float xsq[RN], rmE[RN], rmO[RN];

#pragma unroll
    for (int r = 0; r < RN; r++) {
        const int n = blockIdx.x * BN + r * T + tid;
        const float* pr = rows + (size_t)n * 3;
        const float a0 = pr[0], a1 = pr[1], a2 = pr[2];
        xsq[r] = a0 * a0 + a1 * a1 + a2 * a2;
        PACK2(px0[r], a0);
        PACK2(px1[r], a1);
        PACK2(px2[r], a2);
        rmE[r] = 3.4e38f;
        rmO[r] = 3.4e38f;
    }

    // Shared tile: col pair j -> entry 2j   = {-2y0[e],-2y0[o],-2y1[e],-2y1[o]}
    //                            entry 2j+1 = {-2y2[e],-2y2[o],  y2[e],  y2[o]}
    __shared__ ulonglong2 sAB[TM];
    __shared__ unsigned   sred[T / 32];

    {
        const int c0 = blockIdx.y * CPB;
#pragma unroll
        for (int ii = 0; ii < TM / T; ii++) {
            const int idx = ii * T + tid;
            const float* pc = cols + (size_t)(c0 + idx) * 3;
            const float y0 = pc[0], y1 = pc[1], y2 = pc[2];
            const float ysq = y0 * y0 + y1 * y1 + y2 * y2;
            const int j = idx >> 1, l = idx & 1;
            float* A  = reinterpret_cast<float*>(&sAB[2 * j]);
            float* Bv = reinterpret_cast<float*>(&sAB[2 * j + 1]);
            A[l]      = -2.0f * y0;
            A[2 + l]  = -2.0f * y1;
            Bv[l]     = -2.0f * y2;
            Bv[2 + l] = ysq;
        }
    }
    __syncthreads();

    const ulonglong2* sp = sAB;
#pragma unroll 8
    for (int j = 0; j < TM / 2; j++, sp += 2) {
        const ulonglong2 va = sp[0];
        const ulonglong2 vb = sp[1];
#pragma unroll
        for (int r = 0; r < RN; r++) {
            unsigned long long t0r, t1r, acc;
            FMA2(t0r, px2[r], vb.x, vb.y);   // -2*x2*y2 + y^2
            FMA2(t1r, px1[r], va.y, t0r);    // + -2*x1*y1
            FMA2(acc, px0[r], va.x, t1r);    // + -2*x0*y0
            float lo, hi;
            UNPACK2(lo, hi, acc);
            rmE[r] = fminf(rmE[r], lo);
            rmO[r] = fminf(rmO[r], hi);
        }
    }

    // Combine this slice's row mins into the global per-row key array.
#pragma unroll
    for (int r = 0; r < RN; r++) {
        const int n = blockIdx.x * BN + r * T + tid;
        const float d = xsq[r] + fminf(rmE[r], rmO[r]);
        atomicMax(&g_cmb[z][n], map_min(d));
    }
    __threadfence();
    __syncthreads();

    // Group ticket: last of the GBLK blocks in this (b,dir) finalizes.
    __shared__ int s_last;
    if (tid == 0)
        s_last = (atomicAdd(&g_grp[z], 1) == GBLK - 1);
    __syncthreads();
    if (!s_last) return;
    __threadfence();

    // Group finalize: max over rows of row-min == unmap(min over keys).
    unsigned kmin = 0xFFFFFFFFu;
    for (int i = tid; i < NPOINT; i += T) {
        kmin = min(kmin, g_cmb[z][i]);
        g_cmb[z][i] = 0u;                       // reset for next replay
    }
#pragma unroll
    for (int off = 16; off > 0; off >>= 1)
        kmin = min(kmin, __shfl_xor_sync(0xffffffffu, kmin, off));
    if ((tid & 31) == 0) sred[tid >> 5] = kmin;
    __syncthreads();

    if (tid == 0) {
        unsigned km = sred[0];
#pragma unroll
        for (int w = 1; w < T / 32; w++) km = min(km, sred[w]);
        float m = fmaxf(unmap_min(km), 0.0f);   // true max > 0
        atomicMax(reinterpret_cast<int*>(&g_bmax[b]), __float_as_int(m));
        g_grp[z] = 0;                           // reset group ticket
        __threadfence();
        if (atomicAdd(&g_done, 1) == NGRP - 1) {
            __threadfence();
            float s = 0.0f;
            for (int i = 0; i < nb; i++) {
                s += g_bmax[i];
                g_bmax[i] = 0.0f;               // reset
            }
            out[0] = s;
            __threadfence();
            atomicExch(&g_done, 0);             // reset
        }
    }
}

extern "C" void kernel_launch(void* const* d_in, const int* in_sizes, int n_in,
                              void* d_out, int out_size) {
    const float* p1 = (const float*)d_in[0];
    const float* p2 = (const float*)d_in[1];
    float* out = (float*)d_out;

    const int B = in_sizes[0] / (NPOINT * 3);
    dim3 grid(ROWB, CS, B * 2);
    hd_main<<<grid, T>>>(p1, p2, out, B);
}